// round 2
// baseline (speedup 1.0000x reference)
#include <cuda_runtime.h>

// ---------------------------------------------------------------------------
// GCN5: 5-layer GCN (128->128->128->128->64->32) + mean pool + FC (32->10)
// N = 100000 nodes, E = 1.6M edges, 64 graphs.
// NOTE: edge_index / batch arrive as int32 (JAX x64 disabled).
// Strategy: per layer  T = H @ W  (shared-tiled fp32 GEMM),
//           A[dst] += dinv[src]*dinv[dst]*T[src]  (vector red.global.add.v4),
//           H = relu(A + dinv^2 * T + b)          (self-loop + bias + relu)
// All scratch in __device__ globals (no allocation allowed).
// ---------------------------------------------------------------------------

#define MAXN 100000
#define MAXF 128
#define NGRAPH 64

__device__ float g_T[MAXN * MAXF];     // post-GEMM features
__device__ float g_A[MAXN * MAXF];     // aggregation accumulator
__device__ float g_H[MAXN * MAXF];     // layer activations
__device__ float g_dinv[MAXN];         // deg^{-1/2} (deg incl. self loop)
__device__ float g_pool[NGRAPH * 32];  // per-graph feature sums
__device__ float g_cnt[NGRAPH];        // per-graph node counts

// ---------------- degree / normalization ----------------
__global__ void k_deg_init(int N) {
    int i = blockIdx.x * blockDim.x + threadIdx.x;
    if (i < N) g_dinv[i] = 1.0f;  // self loop contributes 1 to target degree
}

__global__ void k_deg_edges(const int* __restrict__ ei, int E) {
    int e = blockIdx.x * blockDim.x + threadIdx.x;
    if (e < E) {
        int d = ei[E + e];  // dst row of edge_index
        atomicAdd(&g_dinv[d], 1.0f);
    }
}

__global__ void k_deg_fin(int N) {
    int i = blockIdx.x * blockDim.x + threadIdx.x;
    if (i < N) g_dinv[i] = rsqrtf(g_dinv[i]);
}

// ---------------- GEMM: T[N,M] = Hin[N,K] @ W[K,M] ----------------
// Block: M threads, 32 node-rows per block. K chunked by 64.
// Shared: W chunk [64,M] + H chunk [32,64].
template <int M>
__global__ void k_gemm(const float* __restrict__ Xin, int use_x,
                       const float* __restrict__ W, int N, int K) {
    const float* __restrict__ Hin = use_x ? Xin : g_H;
    __shared__ float Ws[64 * M];
    __shared__ float Hs[32 * 64];
    const int tid = threadIdx.x;
    const int node0 = blockIdx.x * 32;

    float acc[32];
#pragma unroll
    for (int n = 0; n < 32; n++) acc[n] = 0.0f;

    for (int k0 = 0; k0 < K; k0 += 64) {
        // load W chunk (coalesced: tid over M columns)
#pragma unroll 8
        for (int k = 0; k < 64; k++) Ws[k * M + tid] = W[(k0 + k) * M + tid];
        // load H chunk
        for (int idx = tid; idx < 32 * 64; idx += M) {
            int n = idx >> 6, k = idx & 63;
            int row = node0 + n;
            Hs[idx] = (row < N) ? Hin[(long long)row * K + k0 + k] : 0.0f;
        }
        __syncthreads();

#pragma unroll 2
        for (int k = 0; k < 64; k += 4) {
            float w0 = Ws[(k + 0) * M + tid];
            float w1 = Ws[(k + 1) * M + tid];
            float w2 = Ws[(k + 2) * M + tid];
            float w3 = Ws[(k + 3) * M + tid];
#pragma unroll
            for (int n = 0; n < 32; n++) {
                float4 h = *(const float4*)&Hs[n * 64 + k];
                float a = acc[n];
                a = fmaf(h.x, w0, a);
                a = fmaf(h.y, w1, a);
                a = fmaf(h.z, w2, a);
                a = fmaf(h.w, w3, a);
                acc[n] = a;
            }
        }
        __syncthreads();
    }

#pragma unroll
    for (int n = 0; n < 32; n++) {
        int row = node0 + n;
        if (row < N) g_T[(long long)row * M + tid] = acc[n];
    }
}

// ---------------- zero accumulator ----------------
__global__ void k_zeroA(long long n4) {
    long long i = blockIdx.x * (long long)blockDim.x + threadIdx.x;
    if (i < n4) ((float4*)g_A)[i] = make_float4(0.f, 0.f, 0.f, 0.f);
}

// ---------------- edge scatter: A[dst] += norm * T[src] ----------------
// One thread per (edge, float4-chunk). For F=128 one warp == one edge, so
// edge-index / dinv loads are warp-uniform (broadcast).
__global__ void k_scatter(const int* __restrict__ ei, int E, int F, int cshift) {
    long long tid = blockIdx.x * (long long)blockDim.x + threadIdx.x;
    long long e = tid >> cshift;
    if (e >= E) return;
    int c = (int)(tid & ((1 << cshift) - 1));
    int s = ei[e];
    int d = ei[E + e];
    float nrm = g_dinv[s] * g_dinv[d];
    float4 v = *(const float4*)&g_T[(long long)s * F + (c << 2)];
    float* dst = &g_A[(long long)d * F + (c << 2)];
    asm volatile(
        "red.global.add.v4.f32 [%0], {%1, %2, %3, %4};"
        :: "l"(dst), "f"(v.x * nrm), "f"(v.y * nrm), "f"(v.z * nrm), "f"(v.w * nrm)
        : "memory");
}

// ---------------- finalize: H = relu(A + dinv^2 * T + b) ----------------
__global__ void k_finalize(const float* __restrict__ b, long long total, int fshift, int F) {
    long long idx = blockIdx.x * (long long)blockDim.x + threadIdx.x;
    if (idx >= total) return;
    int i = (int)(idx >> fshift);
    int c = (int)(idx & (F - 1));
    float dv = g_dinv[i];
    float v = fmaf(dv * dv, g_T[idx], g_A[idx]) + b[c];
    g_H[idx] = fmaxf(v, 0.0f);
}

// ---------------- pooling ----------------
__global__ void k_zero_pool() {
    int i = blockIdx.x * blockDim.x + threadIdx.x;
    if (i < NGRAPH * 32) g_pool[i] = 0.0f;
    if (i < NGRAPH) g_cnt[i] = 0.0f;
}

__global__ void k_pool(const int* __restrict__ batch, int N) {
    int idx = blockIdx.x * blockDim.x + threadIdx.x;
    if (idx >= N * 32) return;
    int i = idx >> 5, c = idx & 31;
    int g = batch[i];
    atomicAdd(&g_pool[g * 32 + c], g_H[idx]);
    if (c == 0) atomicAdd(&g_cnt[g], 1.0f);
}

// ---------------- FC: out[64,10] = (pool/cnt) @ Wfc + bfc ----------------
__global__ void k_fc(const float* __restrict__ Wfc, const float* __restrict__ bfc,
                     float* __restrict__ out) {
    int t = threadIdx.x;
    if (t >= NGRAPH * 10) return;
    int g = t / 10, o = t % 10;
    float inv = 1.0f / fmaxf(g_cnt[g], 1.0f);
    float s = bfc[o];
#pragma unroll
    for (int k = 0; k < 32; k++) s = fmaf(g_pool[g * 32 + k] * inv, Wfc[k * 10 + o], s);
    out[g * 10 + o] = s;
}

// ---------------------------------------------------------------------------
extern "C" void kernel_launch(void* const* d_in, const int* in_sizes, int n_in,
                              void* d_out, int out_size) {
    const float* x = (const float*)d_in[0];
    const int* ei = (const int*)d_in[1];
    const int* batch = (const int*)d_in[2];
    const float* W[5] = {(const float*)d_in[3], (const float*)d_in[5],
                         (const float*)d_in[7], (const float*)d_in[9],
                         (const float*)d_in[11]};
    const float* b[5] = {(const float*)d_in[4], (const float*)d_in[6],
                         (const float*)d_in[8], (const float*)d_in[10],
                         (const float*)d_in[12]};
    const float* Wfc = (const float*)d_in[13];
    const float* bfc = (const float*)d_in[14];
    float* out = (float*)d_out;

    int N = in_sizes[0] / 128;
    int E = in_sizes[1] / 2;

    // normalization coefficients
    k_deg_init<<<(N + 255) / 256, 256>>>(N);
    k_deg_edges<<<(E + 255) / 256, 256>>>(ei, E);
    k_deg_fin<<<(N + 255) / 256, 256>>>(N);

    const int Kd[5] = {128, 128, 128, 128, 64};
    const int Md[5] = {128, 128, 128, 64, 32};

    for (int l = 0; l < 5; l++) {
        int K = Kd[l], M = Md[l];
        int grid = (N + 31) / 32;
        if (M == 128)
            k_gemm<128><<<grid, 128>>>(x, l == 0 ? 1 : 0, W[l], N, K);
        else if (M == 64)
            k_gemm<64><<<grid, 64>>>(x, 0, W[l], N, K);
        else
            k_gemm<32><<<grid, 32>>>(x, 0, W[l], N, K);

        long long n4 = (long long)N * M / 4;
        k_zeroA<<<(int)((n4 + 255) / 256), 256>>>(n4);

        int cshift = (M == 128) ? 5 : (M == 64) ? 4 : 3;  // float4 chunks per row
        long long work = (long long)E << cshift;
        k_scatter<<<(int)((work + 255) / 256), 256>>>(ei, E, M, cshift);

        int fshift = (M == 128) ? 7 : (M == 64) ? 6 : 5;
        long long nf = (long long)N * M;
        k_finalize<<<(int)((nf + 255) / 256), 256>>>(b[l], nf, fshift, M);
    }

    k_zero_pool<<<(NGRAPH * 32 + 255) / 256, 256>>>();
    k_pool<<<(N * 32 + 255) / 256, 256>>>(batch, N);
    k_fc<<<1, NGRAPH * 10>>>(Wfc, bfc, out);
}

// round 4
// speedup vs baseline: 2.2648x; 2.2648x over previous
#include <cuda_runtime.h>

// ---------------------------------------------------------------------------
// GCN5 — R3: same as R2 (CSR-gather aggregation + register-blocked GEMM)
// with the pool-zeroing launch bug fixed (must cover all NGRAPH*32 entries,
// otherwise replays accumulate into stale g_pool -> post-timing divergence).
// ---------------------------------------------------------------------------

#define MAXN 100000
#define MAXE 1600000
#define MAXF 128
#define NGRAPH 64
#define SCAN_BLK 256

__device__ float g_T[MAXN * MAXF];      // post-GEMM features
__device__ float g_H[MAXN * MAXF];      // layer activations
__device__ float g_dinv[MAXN];          // deg^{-1/2} (incl. self loop)
__device__ int   g_cnt_i[MAXN];         // in-degree histogram
__device__ int   g_rowptr[MAXN + 1];    // CSR row pointers (by dst)
__device__ int   g_cursor[MAXN];        // fill cursors
__device__ int   g_csrc[MAXE];          // CSR src indices
__device__ float g_cnorm[MAXE];         // per-edge norm dinv[s]*dinv[d]
__device__ int   g_bsum[512];           // scan block sums (inclusive)
__device__ float g_pool[NGRAPH * 32];
__device__ float g_cnt[NGRAPH];

// ---------------- CSR build ----------------
__global__ void k_zero_cnt(int N) {
    int i = blockIdx.x * blockDim.x + threadIdx.x;
    if (i < N) g_cnt_i[i] = 0;
}

__global__ void k_count(const int* __restrict__ ei, int E) {
    int e = blockIdx.x * blockDim.x + threadIdx.x;
    if (e < E) atomicAdd(&g_cnt_i[ei[E + e]], 1);
}

__global__ void k_scan1(int N) {
    __shared__ int sh[SCAN_BLK];
    int tid = threadIdx.x;
    int i = blockIdx.x * SCAN_BLK + tid;
    sh[tid] = (i < N) ? g_cnt_i[i] : 0;
    __syncthreads();
#pragma unroll
    for (int o = 1; o < SCAN_BLK; o <<= 1) {
        int t = (tid >= o) ? sh[tid - o] : 0;
        __syncthreads();
        sh[tid] += t;
        __syncthreads();
    }
    if (i < N) g_rowptr[i + 1] = sh[tid];
    if (tid == SCAN_BLK - 1) g_bsum[blockIdx.x] = sh[tid];
}

__global__ void k_scan2(int nb) {
    __shared__ int sh[512];
    int tid = threadIdx.x;
    sh[tid] = (tid < nb) ? g_bsum[tid] : 0;
    __syncthreads();
#pragma unroll
    for (int o = 1; o < 512; o <<= 1) {
        int t = (tid >= o) ? sh[tid - o] : 0;
        __syncthreads();
        sh[tid] += t;
        __syncthreads();
    }
    if (tid < nb) g_bsum[tid] = sh[tid];
}

__global__ void k_scan3(int N) {
    int i = blockIdx.x * SCAN_BLK + threadIdx.x;
    if (i < N && blockIdx.x > 0) g_rowptr[i + 1] += g_bsum[blockIdx.x - 1];
    if (i == 0) g_rowptr[0] = 0;
}

__global__ void k_dinv(int N) {
    int i = blockIdx.x * blockDim.x + threadIdx.x;
    if (i < N) {
        float deg = (float)(g_rowptr[i + 1] - g_rowptr[i]) + 1.0f;  // + self loop
        g_dinv[i] = rsqrtf(deg);
        g_cursor[i] = 0;
    }
}

__global__ void k_fill(const int* __restrict__ ei, int E) {
    int e = blockIdx.x * blockDim.x + threadIdx.x;
    if (e >= E) return;
    int s = ei[e];
    int d = ei[E + e];
    int pos = atomicAdd(&g_cursor[d], 1);
    int idx = g_rowptr[d] + pos;
    g_csrc[idx] = s;
    g_cnorm[idx] = g_dinv[s] * g_dinv[d];
}

// ---------------- GEMM: T[N,M] = Hin[N,K] @ W[K,M] ----------------
// 64 rows x M cols per block, 2M threads, 8 rows x 4 cols per thread.
template <int M>
__global__ void k_gemm(const float* __restrict__ Xin, int use_x,
                       const float* __restrict__ W, int N, int K) {
    const float* __restrict__ Hin = use_x ? Xin : g_H;
    constexpr int THREADS = 2 * M;
    constexpr int COLG = M / 4;
    __shared__ float Ws[32 * M];
    __shared__ float Hs[64 * 36];
    const int tid = threadIdx.x;
    const int colg = tid % COLG;
    const int rowg = tid / COLG;  // 0..7
    const int node0 = blockIdx.x * 64;

    float4 acc[8];
#pragma unroll
    for (int r = 0; r < 8; r++) acc[r] = make_float4(0.f, 0.f, 0.f, 0.f);

    for (int k0 = 0; k0 < K; k0 += 32) {
        // load W chunk [32, M] (coalesced float4)
        for (int i = tid; i < 8 * M; i += THREADS)
            ((float4*)Ws)[i] = ((const float4*)(W + k0 * M))[i];
        // load H chunk [64, 32] into padded rows of 36 floats
        for (int i = tid; i < 64 * 8; i += THREADS) {
            int r = i >> 3, k4 = i & 7;
            int row = node0 + r;
            float4 v = make_float4(0.f, 0.f, 0.f, 0.f);
            if (row < N) v = ((const float4*)(Hin + (long long)row * K + k0))[k4];
            *(float4*)&Hs[r * 36 + k4 * 4] = v;
        }
        __syncthreads();

#pragma unroll
        for (int k = 0; k < 32; k++) {
            float4 w = *(float4*)&Ws[k * M + colg * 4];
            float h[8];
#pragma unroll
            for (int r = 0; r < 8; r++) h[r] = Hs[(rowg * 8 + r) * 36 + k];
#pragma unroll
            for (int r = 0; r < 8; r++) {
                acc[r].x = fmaf(h[r], w.x, acc[r].x);
                acc[r].y = fmaf(h[r], w.y, acc[r].y);
                acc[r].z = fmaf(h[r], w.z, acc[r].z);
                acc[r].w = fmaf(h[r], w.w, acc[r].w);
            }
        }
        __syncthreads();
    }

#pragma unroll
    for (int r = 0; r < 8; r++) {
        int row = node0 + rowg * 8 + r;
        if (row < N) ((float4*)(g_T + (long long)row * M))[colg] = acc[r];
    }
}

// ---------------- fused aggregation: H = relu(dinv^2*T + gather + b) -------
template <int CH>
__global__ void k_agg(const float* __restrict__ bias, int N) {
    const int nodesPerBlk = blockDim.x / CH;
    const int grp = threadIdx.x / CH;
    const int c = threadIdx.x % CH;
    const int node = blockIdx.x * nodesPerBlk + grp;
    if (node >= N) return;

    const float4* __restrict__ T4 = (const float4*)g_T;
    int j = g_rowptr[node];
    const int jend = g_rowptr[node + 1];
    float dv = g_dinv[node];
    float sl = dv * dv;

    float4 t = T4[(long long)node * CH + c];
    float4 acc = make_float4(t.x * sl, t.y * sl, t.z * sl, t.w * sl);

    for (; j + 4 <= jend; j += 4) {
        int s0 = g_csrc[j], s1 = g_csrc[j + 1], s2 = g_csrc[j + 2], s3 = g_csrc[j + 3];
        float n0 = g_cnorm[j], n1 = g_cnorm[j + 1], n2 = g_cnorm[j + 2], n3 = g_cnorm[j + 3];
        float4 v0 = T4[(long long)s0 * CH + c];
        float4 v1 = T4[(long long)s1 * CH + c];
        float4 v2 = T4[(long long)s2 * CH + c];
        float4 v3 = T4[(long long)s3 * CH + c];
        acc.x = fmaf(n0, v0.x, acc.x); acc.y = fmaf(n0, v0.y, acc.y);
        acc.z = fmaf(n0, v0.z, acc.z); acc.w = fmaf(n0, v0.w, acc.w);
        acc.x = fmaf(n1, v1.x, acc.x); acc.y = fmaf(n1, v1.y, acc.y);
        acc.z = fmaf(n1, v1.z, acc.z); acc.w = fmaf(n1, v1.w, acc.w);
        acc.x = fmaf(n2, v2.x, acc.x); acc.y = fmaf(n2, v2.y, acc.y);
        acc.z = fmaf(n2, v2.z, acc.z); acc.w = fmaf(n2, v2.w, acc.w);
        acc.x = fmaf(n3, v3.x, acc.x); acc.y = fmaf(n3, v3.y, acc.y);
        acc.z = fmaf(n3, v3.z, acc.z); acc.w = fmaf(n3, v3.w, acc.w);
    }
    for (; j < jend; j++) {
        int s = g_csrc[j];
        float nn = g_cnorm[j];
        float4 v = T4[(long long)s * CH + c];
        acc.x = fmaf(nn, v.x, acc.x); acc.y = fmaf(nn, v.y, acc.y);
        acc.z = fmaf(nn, v.z, acc.z); acc.w = fmaf(nn, v.w, acc.w);
    }

    float4 bb = ((const float4*)bias)[c];
    acc.x = fmaxf(acc.x + bb.x, 0.f);
    acc.y = fmaxf(acc.y + bb.y, 0.f);
    acc.z = fmaxf(acc.z + bb.z, 0.f);
    acc.w = fmaxf(acc.w + bb.w, 0.f);
    ((float4*)g_H)[(long long)node * CH + c] = acc;
}

// ---------------- pooling + FC ----------------
__global__ void k_zero_pool() {
    int i = blockIdx.x * blockDim.x + threadIdx.x;
    if (i < NGRAPH * 32) g_pool[i] = 0.0f;
    if (i < NGRAPH) g_cnt[i] = 0.0f;
}

__global__ void k_pool(const int* __restrict__ batch, int N) {
    int idx = blockIdx.x * blockDim.x + threadIdx.x;
    if (idx >= N * 32) return;
    int i = idx >> 5, c = idx & 31;
    int g = batch[i];
    atomicAdd(&g_pool[g * 32 + c], g_H[idx]);
    if (c == 0) atomicAdd(&g_cnt[g], 1.0f);
}

__global__ void k_fc(const float* __restrict__ Wfc, const float* __restrict__ bfc,
                     float* __restrict__ out) {
    int t = threadIdx.x;
    if (t >= NGRAPH * 10) return;
    int g = t / 10, o = t % 10;
    float inv = 1.0f / fmaxf(g_cnt[g], 1.0f);
    float s = bfc[o];
#pragma unroll
    for (int k = 0; k < 32; k++) s = fmaf(g_pool[g * 32 + k] * inv, Wfc[k * 10 + o], s);
    out[g * 10 + o] = s;
}

// ---------------------------------------------------------------------------
extern "C" void kernel_launch(void* const* d_in, const int* in_sizes, int n_in,
                              void* d_out, int out_size) {
    const float* x = (const float*)d_in[0];
    const int* ei = (const int*)d_in[1];
    const int* batch = (const int*)d_in[2];
    const float* W[5] = {(const float*)d_in[3], (const float*)d_in[5],
                         (const float*)d_in[7], (const float*)d_in[9],
                         (const float*)d_in[11]};
    const float* b[5] = {(const float*)d_in[4], (const float*)d_in[6],
                         (const float*)d_in[8], (const float*)d_in[10],
                         (const float*)d_in[12]};
    const float* Wfc = (const float*)d_in[13];
    const float* bfc = (const float*)d_in[14];
    float* out = (float*)d_out;

    int N = in_sizes[0] / 128;
    int E = in_sizes[1] / 2;
    int nb = (N + SCAN_BLK - 1) / SCAN_BLK;

    // CSR build + normalization
    k_zero_cnt<<<(N + 255) / 256, 256>>>(N);
    k_count<<<(E + 255) / 256, 256>>>(ei, E);
    k_scan1<<<nb, SCAN_BLK>>>(N);
    k_scan2<<<1, 512>>>(nb);
    k_scan3<<<nb, SCAN_BLK>>>(N);
    k_dinv<<<(N + 255) / 256, 256>>>(N);
    k_fill<<<(E + 255) / 256, 256>>>(ei, E);

    int grid64 = (N + 63) / 64;
    // L1..L3: 128->128
    k_gemm<128><<<grid64, 256>>>(x, 1, W[0], N, 128);
    k_agg<32><<<(N + 7) / 8, 256>>>(b[0], N);
    k_gemm<128><<<grid64, 256>>>(x, 0, W[1], N, 128);
    k_agg<32><<<(N + 7) / 8, 256>>>(b[1], N);
    k_gemm<128><<<grid64, 256>>>(x, 0, W[2], N, 128);
    k_agg<32><<<(N + 7) / 8, 256>>>(b[2], N);
    // L4: 128->64
    k_gemm<64><<<grid64, 128>>>(x, 0, W[3], N, 128);
    k_agg<16><<<(N + 15) / 16, 256>>>(b[3], N);
    // L5: 64->32
    k_gemm<32><<<grid64, 64>>>(x, 0, W[4], N, 64);
    k_agg<8><<<(N + 31) / 32, 256>>>(b[4], N);

    // FIX: cover all NGRAPH*32 pool entries (was <<<1,256>>> -> stale pool on replay)
    k_zero_pool<<<(NGRAPH * 32 + 255) / 256, 256>>>();
    k_pool<<<(N * 32 + 255) / 256, 256>>>(batch, N);
    k_fc<<<1, NGRAPH * 10>>>(Wfc, bfc, out);
}

// round 5
// speedup vs baseline: 2.7206x; 1.2013x over previous
#include <cuda_runtime.h>
#include <cuda_bf16.h>

// ---------------------------------------------------------------------------
// GCN5 — R4: FFMA2 (fma.rn.f32x2) GEMM + bf16 T for the L2 gather + warp pool.
// Per layer:  Tb = bf16(H @ W)     (64 x M tile GEMM, 8x4 microtile, f32x2 FMA)
//             H  = relu(dinv^2*Tb + sum_in cnorm*Tb[src] + b)  (fp32 accum)
// CSR built once per launch (int32 edge_index).
// ---------------------------------------------------------------------------

#define MAXN 100000
#define MAXE 1600000
#define MAXF 128
#define NGRAPH 64
#define SCAN_BLK 256

__device__ __align__(16) __nv_bfloat16 g_Tb[MAXN * MAXF];  // post-GEMM (bf16)
__device__ float g_H[MAXN * MAXF];      // layer activations (fp32)
__device__ float g_dinv[MAXN];          // deg^{-1/2} (incl. self loop)
__device__ int   g_cnt_i[MAXN];         // in-degree histogram
__device__ int   g_rowptr[MAXN + 1];    // CSR row pointers (by dst)
__device__ int   g_cursor[MAXN];        // fill cursors
__device__ int   g_csrc[MAXE];          // CSR src indices
__device__ float g_cnorm[MAXE];         // per-edge norm dinv[s]*dinv[d]
__device__ int   g_bsum[512];           // scan block sums (inclusive)
__device__ float g_pool[NGRAPH * 32];
__device__ float g_cnt[NGRAPH];

// ---------------- f32x2 helpers (FFMA2) ----------------
__device__ __forceinline__ unsigned long long f32x2_dup(float h) {
    unsigned long long r;
    asm("mov.b64 %0, {%1, %1};" : "=l"(r) : "f"(h));
    return r;
}
__device__ __forceinline__ void f32x2_fma(unsigned long long& d,
                                          unsigned long long a,
                                          unsigned long long b) {
    asm("fma.rn.f32x2 %0, %1, %2, %0;" : "+l"(d) : "l"(a), "l"(b));
}
__device__ __forceinline__ float2 f32x2_unpack(unsigned long long v) {
    float2 f;
    asm("mov.b64 {%0, %1}, %2;" : "=f"(f.x), "=f"(f.y) : "l"(v));
    return f;
}

// ---------------- CSR build ----------------
__global__ void k_zero_cnt(int N) {
    int i = blockIdx.x * blockDim.x + threadIdx.x;
    if (i < N) g_cnt_i[i] = 0;
}

__global__ void k_count(const int* __restrict__ ei, int E) {
    int e = blockIdx.x * blockDim.x + threadIdx.x;
    if (e < E) atomicAdd(&g_cnt_i[ei[E + e]], 1);
}

__global__ void k_scan1(int N) {
    __shared__ int sh[SCAN_BLK];
    int tid = threadIdx.x;
    int i = blockIdx.x * SCAN_BLK + tid;
    sh[tid] = (i < N) ? g_cnt_i[i] : 0;
    __syncthreads();
#pragma unroll
    for (int o = 1; o < SCAN_BLK; o <<= 1) {
        int t = (tid >= o) ? sh[tid - o] : 0;
        __syncthreads();
        sh[tid] += t;
        __syncthreads();
    }
    if (i < N) g_rowptr[i + 1] = sh[tid];
    if (tid == SCAN_BLK - 1) g_bsum[blockIdx.x] = sh[tid];
}

__global__ void k_scan2(int nb) {
    __shared__ int sh[512];
    int tid = threadIdx.x;
    sh[tid] = (tid < nb) ? g_bsum[tid] : 0;
    __syncthreads();
#pragma unroll
    for (int o = 1; o < 512; o <<= 1) {
        int t = (tid >= o) ? sh[tid - o] : 0;
        __syncthreads();
        sh[tid] += t;
        __syncthreads();
    }
    if (tid < nb) g_bsum[tid] = sh[tid];
}

__global__ void k_scan3(int N) {
    int i = blockIdx.x * SCAN_BLK + threadIdx.x;
    if (i < N && blockIdx.x > 0) g_rowptr[i + 1] += g_bsum[blockIdx.x - 1];
    if (i == 0) g_rowptr[0] = 0;
}

__global__ void k_dinv(int N) {
    int i = blockIdx.x * blockDim.x + threadIdx.x;
    if (i < N) {
        float deg = (float)(g_rowptr[i + 1] - g_rowptr[i]) + 1.0f;  // + self loop
        g_dinv[i] = rsqrtf(deg);
        g_cursor[i] = 0;
    }
}

__global__ void k_fill(const int* __restrict__ ei, int E) {
    int e = blockIdx.x * blockDim.x + threadIdx.x;
    if (e >= E) return;
    int s = ei[e];
    int d = ei[E + e];
    int pos = atomicAdd(&g_cursor[d], 1);
    int idx = g_rowptr[d] + pos;
    g_csrc[idx] = s;
    g_cnorm[idx] = g_dinv[s] * g_dinv[d];
}

// ---------------- GEMM: Tb[N,M] = bf16(Hin[N,K] @ W[K,M]) ----------------
// 64 rows x M cols per block, 2M threads, 8 rows x 4 cols per thread.
// Inner product uses fma.rn.f32x2: W col-pairs alias free from the float4
// shared load (ulonglong2 view); h is duplicated into both lanes.
template <int M>
__global__ void k_gemm(const float* __restrict__ Xin, int use_x,
                       const float* __restrict__ W, int N, int K) {
    const float* __restrict__ Hin = use_x ? Xin : g_H;
    constexpr int THREADS = 2 * M;
    constexpr int COLG = M / 4;
    __shared__ float Ws[32 * M];
    __shared__ float Hs[64 * 36];
    const int tid = threadIdx.x;
    const int colg = tid % COLG;
    const int rowg = tid / COLG;  // 0..7
    const int node0 = blockIdx.x * 64;

    unsigned long long acc[8][2];
#pragma unroll
    for (int r = 0; r < 8; r++) { acc[r][0] = 0ull; acc[r][1] = 0ull; }

    for (int k0 = 0; k0 < K; k0 += 32) {
        // load W chunk [32, M] (coalesced float4)
        for (int i = tid; i < 8 * M; i += THREADS)
            ((float4*)Ws)[i] = ((const float4*)(W + k0 * M))[i];
        // load H chunk [64, 32] into padded rows of 36 floats
        for (int i = tid; i < 64 * 8; i += THREADS) {
            int r = i >> 3, k4 = i & 7;
            int row = node0 + r;
            float4 v = make_float4(0.f, 0.f, 0.f, 0.f);
            if (row < N) v = ((const float4*)(Hin + (long long)row * K + k0))[k4];
            *(float4*)&Hs[r * 36 + k4 * 4] = v;
        }
        __syncthreads();

#pragma unroll
        for (int k = 0; k < 32; k++) {
            ulonglong2 w2 = *(const ulonglong2*)&Ws[k * M + colg * 4];
#pragma unroll
            for (int r = 0; r < 8; r++) {
                unsigned long long hh = f32x2_dup(Hs[(rowg * 8 + r) * 36 + k]);
                f32x2_fma(acc[r][0], hh, w2.x);
                f32x2_fma(acc[r][1], hh, w2.y);
            }
        }
        __syncthreads();
    }

#pragma unroll
    for (int r = 0; r < 8; r++) {
        int row = node0 + rowg * 8 + r;
        if (row < N) {
            float2 a0 = f32x2_unpack(acc[r][0]);
            float2 a1 = f32x2_unpack(acc[r][1]);
            __nv_bfloat162 p0 = __floats2bfloat162_rn(a0.x, a0.y);
            __nv_bfloat162 p1 = __floats2bfloat162_rn(a1.x, a1.y);
            uint2 o;
            o.x = *reinterpret_cast<unsigned*>(&p0);
            o.y = *reinterpret_cast<unsigned*>(&p1);
            *reinterpret_cast<uint2*>(&g_Tb[(long long)row * M + colg * 4]) = o;
        }
    }
}

// ---------------- fused aggregation: H = relu(dinv^2*Tb + gather + b) ------
// CH chunks of 4 bf16 (8B) per node; fp32 accumulation.
template <int CH>
__device__ __forceinline__ float4 ld_bf4(int s, int c) {
    constexpr int F = CH * 4;
    uint2 u = *reinterpret_cast<const uint2*>(&g_Tb[(long long)s * F + c * 4]);
    __nv_bfloat162 b0 = *reinterpret_cast<__nv_bfloat162*>(&u.x);
    __nv_bfloat162 b1 = *reinterpret_cast<__nv_bfloat162*>(&u.y);
    float2 f0 = __bfloat1622float2(b0);
    float2 f1 = __bfloat1622float2(b1);
    return make_float4(f0.x, f0.y, f1.x, f1.y);
}

template <int CH>
__global__ void k_agg(const float* __restrict__ bias, int N) {
    const int nodesPerBlk = blockDim.x / CH;
    const int grp = threadIdx.x / CH;
    const int c = threadIdx.x % CH;
    const int node = blockIdx.x * nodesPerBlk + grp;
    if (node >= N) return;

    int j = g_rowptr[node];
    const int jend = g_rowptr[node + 1];
    float dv = g_dinv[node];
    float sl = dv * dv;

    float4 t = ld_bf4<CH>(node, c);
    float4 acc = make_float4(t.x * sl, t.y * sl, t.z * sl, t.w * sl);

    for (; j + 4 <= jend; j += 4) {
        int s0 = g_csrc[j], s1 = g_csrc[j + 1], s2 = g_csrc[j + 2], s3 = g_csrc[j + 3];
        float n0 = g_cnorm[j], n1 = g_cnorm[j + 1], n2 = g_cnorm[j + 2], n3 = g_cnorm[j + 3];
        float4 v0 = ld_bf4<CH>(s0, c);
        float4 v1 = ld_bf4<CH>(s1, c);
        float4 v2 = ld_bf4<CH>(s2, c);
        float4 v3 = ld_bf4<CH>(s3, c);
        acc.x = fmaf(n0, v0.x, acc.x); acc.y = fmaf(n0, v0.y, acc.y);
        acc.z = fmaf(n0, v0.z, acc.z); acc.w = fmaf(n0, v0.w, acc.w);
        acc.x = fmaf(n1, v1.x, acc.x); acc.y = fmaf(n1, v1.y, acc.y);
        acc.z = fmaf(n1, v1.z, acc.z); acc.w = fmaf(n1, v1.w, acc.w);
        acc.x = fmaf(n2, v2.x, acc.x); acc.y = fmaf(n2, v2.y, acc.y);
        acc.z = fmaf(n2, v2.z, acc.z); acc.w = fmaf(n2, v2.w, acc.w);
        acc.x = fmaf(n3, v3.x, acc.x); acc.y = fmaf(n3, v3.y, acc.y);
        acc.z = fmaf(n3, v3.z, acc.z); acc.w = fmaf(n3, v3.w, acc.w);
    }
    for (; j < jend; j++) {
        int s = g_csrc[j];
        float nn = g_cnorm[j];
        float4 v = ld_bf4<CH>(s, c);
        acc.x = fmaf(nn, v.x, acc.x); acc.y = fmaf(nn, v.y, acc.y);
        acc.z = fmaf(nn, v.z, acc.z); acc.w = fmaf(nn, v.w, acc.w);
    }

    float4 bb = ((const float4*)bias)[c];
    acc.x = fmaxf(acc.x + bb.x, 0.f);
    acc.y = fmaxf(acc.y + bb.y, 0.f);
    acc.z = fmaxf(acc.z + bb.z, 0.f);
    acc.w = fmaxf(acc.w + bb.w, 0.f);
    ((float4*)g_H)[(long long)node * CH + c] = acc;
}

// ---------------- pooling + FC ----------------
__global__ void k_zero_pool() {
    int i = blockIdx.x * blockDim.x + threadIdx.x;
    if (i < NGRAPH * 32) g_pool[i] = 0.0f;
    if (i < NGRAPH) g_cnt[i] = 0.0f;
}

// Warp-chunked pooling: one warp accumulates 32 sorted nodes privately and
// flushes on graph-boundary (batch is sorted), ~32x fewer atomics.
__global__ void k_pool(const int* __restrict__ batch, int N) {
    int warp = (blockIdx.x * blockDim.x + threadIdx.x) >> 5;
    int lane = threadIdx.x & 31;
    int i0 = warp * 32;
    if (i0 >= N) return;
    int iend = min(i0 + 32, N);

    int curg = batch[i0];
    float acc = 0.0f, cnt = 0.0f;
    for (int i = i0; i < iend; i++) {
        int g = batch[i];
        if (g != curg) {
            atomicAdd(&g_pool[curg * 32 + lane], acc);
            if (lane == 0) atomicAdd(&g_cnt[curg], cnt);
            acc = 0.0f; cnt = 0.0f; curg = g;
        }
        acc += g_H[(long long)i * 32 + lane];
        cnt += 1.0f;
    }
    atomicAdd(&g_pool[curg * 32 + lane], acc);
    if (lane == 0) atomicAdd(&g_cnt[curg], cnt);
}

__global__ void k_fc(const float* __restrict__ Wfc, const float* __restrict__ bfc,
                     float* __restrict__ out) {
    int t = threadIdx.x;
    if (t >= NGRAPH * 10) return;
    int g = t / 10, o = t % 10;
    float inv = 1.0f / fmaxf(g_cnt[g], 1.0f);
    float s = bfc[o];
#pragma unroll
    for (int k = 0; k < 32; k++) s = fmaf(g_pool[g * 32 + k] * inv, Wfc[k * 10 + o], s);
    out[g * 10 + o] = s;
}

// ---------------------------------------------------------------------------
extern "C" void kernel_launch(void* const* d_in, const int* in_sizes, int n_in,
                              void* d_out, int out_size) {
    const float* x = (const float*)d_in[0];
    const int* ei = (const int*)d_in[1];
    const int* batch = (const int*)d_in[2];
    const float* W[5] = {(const float*)d_in[3], (const float*)d_in[5],
                         (const float*)d_in[7], (const float*)d_in[9],
                         (const float*)d_in[11]};
    const float* b[5] = {(const float*)d_in[4], (const float*)d_in[6],
                         (const float*)d_in[8], (const float*)d_in[10],
                         (const float*)d_in[12]};
    const float* Wfc = (const float*)d_in[13];
    const float* bfc = (const float*)d_in[14];
    float* out = (float*)d_out;

    int N = in_sizes[0] / 128;
    int E = in_sizes[1] / 2;
    int nb = (N + SCAN_BLK - 1) / SCAN_BLK;

    // CSR build + normalization
    k_zero_cnt<<<(N + 255) / 256, 256>>>(N);
    k_count<<<(E + 255) / 256, 256>>>(ei, E);
    k_scan1<<<nb, SCAN_BLK>>>(N);
    k_scan2<<<1, 512>>>(nb);
    k_scan3<<<nb, SCAN_BLK>>>(N);
    k_dinv<<<(N + 255) / 256, 256>>>(N);
    k_fill<<<(E + 255) / 256, 256>>>(ei, E);

    int grid64 = (N + 63) / 64;
    // L1..L3: 128->128
    k_gemm<128><<<grid64, 256>>>(x, 1, W[0], N, 128);
    k_agg<32><<<(N + 7) / 8, 256>>>(b[0], N);
    k_gemm<128><<<grid64, 256>>>(x, 0, W[1], N, 128);
    k_agg<32><<<(N + 7) / 8, 256>>>(b[1], N);
    k_gemm<128><<<grid64, 256>>>(x, 0, W[2], N, 128);
    k_agg<32><<<(N + 7) / 8, 256>>>(b[2], N);
    // L4: 128->64
    k_gemm<64><<<grid64, 128>>>(x, 0, W[3], N, 128);
    k_agg<16><<<(N + 15) / 16, 256>>>(b[3], N);
    // L5: 64->32
    k_gemm<32><<<grid64, 64>>>(x, 0, W[4], N, 64);
    k_agg<8><<<(N + 31) / 32, 256>>>(b[4], N);

    k_zero_pool<<<(NGRAPH * 32 + 255) / 256, 256>>>();
    k_pool<<<(N + 255) / 256, 256>>>(batch, N);
    k_fc<<<1, NGRAPH * 10>>>(Wfc, bfc, out);
}

// round 10
// speedup vs baseline: 2.9307x; 1.0772x over previous
#include <cuda_runtime.h>
#include <cuda_bf16.h>
#include <cstdint>

// ---------------------------------------------------------------------------
// GCN5 — R8: tf32 mma.sync GEMM (fp32 H, tf32-rounded only inside the MMA),
// bf16 T for the L2 gather, CSR aggregation, warp pooling.
//   Tb = bf16(H @ W)    (128-node tile, 8 warps, m16n8k8 tf32 MMA)
//   H  = relu(dinv^2*Tb + sum_in cnorm*Tb[src] + b)   (fp32 accum + store)
// ---------------------------------------------------------------------------

#define MAXN 100000
#define MAXE 1600000
#define MAXF 128
#define NGRAPH 64
#define SCAN_BLK 256

__device__ __align__(16) __nv_bfloat16 g_Tb[MAXN * MAXF];  // post-GEMM (bf16)
__device__ float g_H[MAXN * MAXF];       // activations (fp32)
__device__ float g_Wt[MAXF * MAXF];      // W^T, tf32-rounded bits (K-major)
__device__ float g_dinv[MAXN];
__device__ int   g_cnt_i[MAXN];
__device__ int   g_rowptr[MAXN + 1];
__device__ int   g_cursor[MAXN];
__device__ int   g_csrc[MAXE];
__device__ float g_cnorm[MAXE];
__device__ int   g_bsum[512];
__device__ float g_pool[NGRAPH * 32];
__device__ float g_cnt[NGRAPH];

__device__ __forceinline__ uint32_t f2tf32(float f) {
    uint32_t r;
    asm("cvt.rna.tf32.f32 %0, %1;" : "=r"(r) : "f"(f));
    return r;
}

// ---------------- CSR build ----------------
__global__ void k_zero_cnt(int N) {
    int i = blockIdx.x * blockDim.x + threadIdx.x;
    if (i < N) g_cnt_i[i] = 0;
}
__global__ void k_count(const int* __restrict__ ei, int E) {
    int e = blockIdx.x * blockDim.x + threadIdx.x;
    if (e < E) atomicAdd(&g_cnt_i[ei[E + e]], 1);
}
__global__ void k_scan1(int N) {
    __shared__ int sh[SCAN_BLK];
    int tid = threadIdx.x;
    int i = blockIdx.x * SCAN_BLK + tid;
    sh[tid] = (i < N) ? g_cnt_i[i] : 0;
    __syncthreads();
#pragma unroll
    for (int o = 1; o < SCAN_BLK; o <<= 1) {
        int t = (tid >= o) ? sh[tid - o] : 0;
        __syncthreads();
        sh[tid] += t;
        __syncthreads();
    }
    if (i < N) g_rowptr[i + 1] = sh[tid];
    if (tid == SCAN_BLK - 1) g_bsum[blockIdx.x] = sh[tid];
}
__global__ void k_scan2(int nb) {
    __shared__ int sh[512];
    int tid = threadIdx.x;
    sh[tid] = (tid < nb) ? g_bsum[tid] : 0;
    __syncthreads();
#pragma unroll
    for (int o = 1; o < 512; o <<= 1) {
        int t = (tid >= o) ? sh[tid - o] : 0;
        __syncthreads();
        sh[tid] += t;
        __syncthreads();
    }
    if (tid < nb) g_bsum[tid] = sh[tid];
}
__global__ void k_scan3(int N) {
    int i = blockIdx.x * SCAN_BLK + threadIdx.x;
    if (i < N && blockIdx.x > 0) g_rowptr[i + 1] += g_bsum[blockIdx.x - 1];
    if (i == 0) g_rowptr[0] = 0;
}
__global__ void k_dinv(int N) {
    int i = blockIdx.x * blockDim.x + threadIdx.x;
    if (i < N) {
        float deg = (float)(g_rowptr[i + 1] - g_rowptr[i]) + 1.0f;
        g_dinv[i] = rsqrtf(deg);
        g_cursor[i] = 0;
    }
}
__global__ void k_fill(const int* __restrict__ ei, int E) {
    int e = blockIdx.x * blockDim.x + threadIdx.x;
    if (e >= E) return;
    int s = ei[e];
    int d = ei[E + e];
    int pos = atomicAdd(&g_cursor[d], 1);
    int idx = g_rowptr[d] + pos;
    g_csrc[idx] = s;
    g_cnorm[idx] = g_dinv[s] * g_dinv[d];
}

// ---------------- weight prep: g_Wt[n*KIN+k] = tf32(W[k*NOUT+n]) ----------
__global__ void k_wt(const float* __restrict__ W, int NOUT, int KIN) {
    int idx = blockIdx.x * blockDim.x + threadIdx.x;
    if (idx >= NOUT * KIN) return;
    int n = idx / KIN, k = idx % KIN;
    uint32_t t = f2tf32(W[k * NOUT + n]);
    g_Wt[idx] = __uint_as_float(t);
}

// ---------------- tf32 HMMA GEMM: Tb[tile, NOUT] = H @ W ----------------
__device__ __forceinline__ void mma1688(float* d, uint32_t a0, uint32_t a1,
                                        uint32_t a2, uint32_t a3,
                                        uint32_t b0, uint32_t b1) {
    asm volatile(
        "mma.sync.aligned.m16n8k8.row.col.f32.tf32.tf32.f32 "
        "{%0,%1,%2,%3}, {%4,%5,%6,%7}, {%8,%9}, {%0,%1,%2,%3};"
        : "+f"(d[0]), "+f"(d[1]), "+f"(d[2]), "+f"(d[3])
        : "r"(a0), "r"(a1), "r"(a2), "r"(a3), "r"(b0), "r"(b1));
}

// 128 rows per CTA, 256 threads (8 warps).
// NOUT=128: warp grid 4x2, warp tile 32x64 (MI=2, NI=8)
// NOUT=64 : warp grid 8x1, warp tile 16x64 (MI=1, NI=8)
// NOUT=32 : warp grid 8x1, warp tile 16x32 (MI=1, NI=4)
template <int NOUT, int KIN>
__global__ void k_hmma(const float* __restrict__ Xin, int use_x, int N) {
    constexpr int S = KIN + 4;  // padded fp32 stride; bank = (4g+tq)%32, conflict-free
    constexpr int MI = (NOUT == 128) ? 2 : 1;
    constexpr int NI = (NOUT == 32) ? 4 : 8;
    extern __shared__ float smf[];
    float* Hs = smf;             // [128, S] (tf32 bits)
    float* Ws = smf + 128 * S;   // [NOUT, S] (tf32 bits)

    const float* __restrict__ Hin = use_x ? Xin : g_H;
    const int tid = threadIdx.x, wid = tid >> 5, lane = tid & 31;
    const int g = lane >> 2, tq = lane & 3;
    const int node0 = blockIdx.x * 128;
    const int rows0 = (NOUT == 128) ? (wid >> 1) * 32 : wid * 16;
    const int col0 = (NOUT == 128) ? (wid & 1) * 64 : 0;

    // stage A (convert fp32 -> tf32 bits) and W (already tf32 bits)
    for (int idx = tid; idx < 128 * (KIN / 4); idx += 256) {
        int row = idx / (KIN / 4), c4 = (idx % (KIN / 4)) * 4;
        float4 v = make_float4(0.f, 0.f, 0.f, 0.f);
        int grow = node0 + row;
        if (grow < N) v = *(const float4*)&Hin[(size_t)grow * KIN + c4];
        uint4 t = make_uint4(f2tf32(v.x), f2tf32(v.y), f2tf32(v.z), f2tf32(v.w));
        *(uint4*)&Hs[row * S + c4] = t;
    }
    for (int idx = tid; idx < NOUT * (KIN / 4); idx += 256) {
        int row = idx / (KIN / 4), c4 = (idx % (KIN / 4)) * 4;
        *(float4*)&Ws[row * S + c4] = *(const float4*)&g_Wt[(size_t)row * KIN + c4];
    }
    __syncthreads();

    float acc[MI][NI][4];
#pragma unroll
    for (int mi = 0; mi < MI; mi++)
#pragma unroll
        for (int ni = 0; ni < NI; ni++)
#pragma unroll
            for (int i = 0; i < 4; i++) acc[mi][ni][i] = 0.f;

#pragma unroll
    for (int k0 = 0; k0 < KIN; k0 += 8) {
        uint32_t b0[NI], b1[NI];
#pragma unroll
        for (int ni = 0; ni < NI; ni++) {
            const float* wp = &Ws[(col0 + ni * 8 + g) * S + k0 + tq];
            b0[ni] = *(const uint32_t*)wp;
            b1[ni] = *(const uint32_t*)(wp + 4);
        }
#pragma unroll
        for (int mi = 0; mi < MI; mi++) {
            const float* ap = &Hs[(rows0 + mi * 16 + g) * S + k0 + tq];
            uint32_t a0 = *(const uint32_t*)ap;
            uint32_t a1 = *(const uint32_t*)(ap + 8 * S);
            uint32_t a2 = *(const uint32_t*)(ap + 4);
            uint32_t a3 = *(const uint32_t*)(ap + 8 * S + 4);
#pragma unroll
            for (int ni = 0; ni < NI; ni++)
                mma1688(acc[mi][ni], a0, a1, a2, a3, b0[ni], b1[ni]);
        }
    }

    // epilogue: bf16 pack, 32-bit stores (c0,c1) row g, (c2,c3) row g+8
#pragma unroll
    for (int mi = 0; mi < MI; mi++) {
        int r0 = node0 + rows0 + mi * 16 + g;
        int r1 = r0 + 8;
#pragma unroll
        for (int ni = 0; ni < NI; ni++) {
            int col = col0 + ni * 8 + tq * 2;
            if (r0 < N) {
                __nv_bfloat162 p = __floats2bfloat162_rn(acc[mi][ni][0], acc[mi][ni][1]);
                *(uint32_t*)&g_Tb[(size_t)r0 * NOUT + col] = *(uint32_t*)&p;
            }
            if (r1 < N) {
                __nv_bfloat162 p = __floats2bfloat162_rn(acc[mi][ni][2], acc[mi][ni][3]);
                *(uint32_t*)&g_Tb[(size_t)r1 * NOUT + col] = *(uint32_t*)&p;
            }
        }
    }
}

// ---------------- fused aggregation: H = relu(dinv^2*Tb + gather + b) ------
template <int CH>
__device__ __forceinline__ float4 ld_bf4(int s, int c) {
    constexpr int F = CH * 4;
    uint2 u = *reinterpret_cast<const uint2*>(&g_Tb[(size_t)s * F + c * 4]);
    __nv_bfloat162 b0 = *reinterpret_cast<__nv_bfloat162*>(&u.x);
    __nv_bfloat162 b1 = *reinterpret_cast<__nv_bfloat162*>(&u.y);
    float2 f0 = __bfloat1622float2(b0);
    float2 f1 = __bfloat1622float2(b1);
    return make_float4(f0.x, f0.y, f1.x, f1.y);
}

template <int CH>
__global__ void k_agg(const float* __restrict__ bias, int N) {
    const int nodesPerBlk = blockDim.x / CH;
    const int grp = threadIdx.x / CH;
    const int c = threadIdx.x % CH;
    const int node = blockIdx.x * nodesPerBlk + grp;
    if (node >= N) return;

    int j = g_rowptr[node];
    const int jend = g_rowptr[node + 1];
    float dv = g_dinv[node];
    float sl = dv * dv;

    float4 t = ld_bf4<CH>(node, c);
    float4 acc = make_float4(t.x * sl, t.y * sl, t.z * sl, t.w * sl);

    for (; j + 4 <= jend; j += 4) {
        int s0 = g_csrc[j], s1 = g_csrc[j + 1], s2 = g_csrc[j + 2], s3 = g_csrc[j + 3];
        float n0 = g_cnorm[j], n1 = g_cnorm[j + 1], n2 = g_cnorm[j + 2], n3 = g_cnorm[j + 3];
        float4 v0 = ld_bf4<CH>(s0, c);
        float4 v1 = ld_bf4<CH>(s1, c);
        float4 v2 = ld_bf4<CH>(s2, c);
        float4 v3 = ld_bf4<CH>(s3, c);
        acc.x = fmaf(n0, v0.x, acc.x); acc.y = fmaf(n0, v0.y, acc.y);
        acc.z = fmaf(n0, v0.z, acc.z); acc.w = fmaf(n0, v0.w, acc.w);
        acc.x = fmaf(n1, v1.x, acc.x); acc.y = fmaf(n1, v1.y, acc.y);
        acc.z = fmaf(n1, v1.z, acc.z); acc.w = fmaf(n1, v1.w, acc.w);
        acc.x = fmaf(n2, v2.x, acc.x); acc.y = fmaf(n2, v2.y, acc.y);
        acc.z = fmaf(n2, v2.z, acc.z); acc.w = fmaf(n2, v2.w, acc.w);
        acc.x = fmaf(n3, v3.x, acc.x); acc.y = fmaf(n3, v3.y, acc.y);
        acc.z = fmaf(n3, v3.z, acc.z); acc.w = fmaf(n3, v3.w, acc.w);
    }
    for (; j < jend; j++) {
        int s = g_csrc[j];
        float nn = g_cnorm[j];
        float4 v = ld_bf4<CH>(s, c);
        acc.x = fmaf(nn, v.x, acc.x); acc.y = fmaf(nn, v.y, acc.y);
        acc.z = fmaf(nn, v.z, acc.z); acc.w = fmaf(nn, v.w, acc.w);
    }

    float4 bb = ((const float4*)bias)[c];
    acc.x = fmaxf(acc.x + bb.x, 0.f);
    acc.y = fmaxf(acc.y + bb.y, 0.f);
    acc.z = fmaxf(acc.z + bb.z, 0.f);
    acc.w = fmaxf(acc.w + bb.w, 0.f);
    ((float4*)g_H)[(size_t)node * CH + c] = acc;
}

// ---------------- pooling + FC ----------------
__global__ void k_zero_pool() {
    int i = blockIdx.x * blockDim.x + threadIdx.x;
    if (i < NGRAPH * 32) g_pool[i] = 0.0f;
    if (i < NGRAPH) g_cnt[i] = 0.0f;
}

__global__ void k_pool(const int* __restrict__ batch, int N) {
    int warp = (blockIdx.x * blockDim.x + threadIdx.x) >> 5;
    int lane = threadIdx.x & 31;
    int i0 = warp * 32;
    if (i0 >= N) return;
    int iend = min(i0 + 32, N);

    int curg = batch[i0];
    float acc = 0.0f, cnt = 0.0f;
    for (int i = i0; i < iend; i++) {
        int g = batch[i];
        if (g != curg) {
            atomicAdd(&g_pool[curg * 32 + lane], acc);
            if (lane == 0) atomicAdd(&g_cnt[curg], cnt);
            acc = 0.0f; cnt = 0.0f; curg = g;
        }
        acc += g_H[(size_t)i * 32 + lane];
        cnt += 1.0f;
    }
    atomicAdd(&g_pool[curg * 32 + lane], acc);
    if (lane == 0) atomicAdd(&g_cnt[curg], cnt);
}

__global__ void k_fc(const float* __restrict__ Wfc, const float* __restrict__ bfc,
                     float* __restrict__ out) {
    int t = threadIdx.x;
    if (t >= NGRAPH * 10) return;
    int g = t / 10, o = t % 10;
    float inv = 1.0f / fmaxf(g_cnt[g], 1.0f);
    float s = bfc[o];
#pragma unroll
    for (int k = 0; k < 32; k++) s = fmaf(g_pool[g * 32 + k] * inv, Wfc[k * 10 + o], s);
    out[g * 10 + o] = s;
}

// ---------------------------------------------------------------------------
extern "C" void kernel_launch(void* const* d_in, const int* in_sizes, int n_in,
                              void* d_out, int out_size) {
    const float* x = (const float*)d_in[0];
    const int* ei = (const int*)d_in[1];
    const int* batch = (const int*)d_in[2];
    const float* W[5] = {(const float*)d_in[3], (const float*)d_in[5],
                         (const float*)d_in[7], (const float*)d_in[9],
                         (const float*)d_in[11]};
    const float* b[5] = {(const float*)d_in[4], (const float*)d_in[6],
                         (const float*)d_in[8], (const float*)d_in[10],
                         (const float*)d_in[12]};
    const float* Wfc = (const float*)d_in[13];
    const float* bfc = (const float*)d_in[14];
    float* out = (float*)d_out;

    int N = in_sizes[0] / 128;
    int E = in_sizes[1] / 2;
    int nb = (N + SCAN_BLK - 1) / SCAN_BLK;

    // dynamic smem: (128 + NOUT) * (KIN+4) * 4 bytes
    const int smem128 = (128 + 128) * 132 * 4;  // 135168
    const int smem64 = (128 + 64) * 132 * 4;    // 101376
    const int smem32 = (128 + 32) * 68 * 4;     // 43520
    cudaFuncSetAttribute(k_hmma<128, 128>, cudaFuncAttributeMaxDynamicSharedMemorySize, smem128);
    cudaFuncSetAttribute(k_hmma<64, 128>, cudaFuncAttributeMaxDynamicSharedMemorySize, smem64);
    cudaFuncSetAttribute(k_hmma<32, 64>, cudaFuncAttributeMaxDynamicSharedMemorySize, smem32);

    // CSR build + normalization
    k_zero_cnt<<<(N + 255) / 256, 256>>>(N);
    k_count<<<(E + 255) / 256, 256>>>(ei, E);
    k_scan1<<<nb, SCAN_BLK>>>(N);
    k_scan2<<<1, 512>>>(nb);
    k_scan3<<<nb, SCAN_BLK>>>(N);
    k_dinv<<<(N + 255) / 256, 256>>>(N);
    k_fill<<<(E + 255) / 256, 256>>>(ei, E);

    int gridT = (N + 127) / 128;
    // L1..L3: 128->128
    for (int l = 0; l < 3; l++) {
        k_wt<<<(128 * 128 + 255) / 256, 256>>>(W[l], 128, 128);
        k_hmma<128, 128><<<gridT, 256, smem128>>>(x, l == 0 ? 1 : 0, N);
        k_agg<32><<<(N + 7) / 8, 256>>>(b[l], N);
    }
    // L4: 128->64
    k_wt<<<(64 * 128 + 255) / 256, 256>>>(W[3], 64, 128);
    k_hmma<64, 128><<<gridT, 256, smem64>>>(x, 0, N);
    k_agg<16><<<(N + 15) / 16, 256>>>(b[3], N);
    // L5: 64->32
    k_wt<<<(32 * 64 + 255) / 256, 256>>>(W[4], 32, 64);
    k_hmma<32, 64><<<gridT, 256, smem32>>>(x, 0, N);
    k_agg<8><<<(N + 31) / 32, 256>>>(b[4], N);

    k_zero_pool<<<(NGRAPH * 32 + 255) / 256, 256>>>();
    k_pool<<<(N + 255) / 256, 256>>>(batch, N);
    k_fc<<<1, NGRAPH * 10>>>(Wfc, bfc, out);
}